// round 11
// baseline (speedup 1.0000x reference)
#include <cuda_runtime.h>
#include <cstdint>

// ---------------------------------------------------------------------------
// Problem constants
// ---------------------------------------------------------------------------
#define T_MSG 8
#define N_TOK 8192
#define LAT 1024
#define SYM 256
#define NC 512

#define OUT_QUANT_OFF ((size_t)N_TOK * LAT)
#define OUT_IDX_OFF   (OUT_QUANT_OFF + (size_t)N_TOK * SYM)
#define OUT_KEEP_OFF  (OUT_IDX_OFF + (size_t)N_TOK)

// ---------------------------------------------------------------------------
// Device scratch (fp32 everywhere; tf32 split happens in registers)
// ---------------------------------------------------------------------------
__device__ float g_ctx[(size_t)N_TOK * LAT];
__device__ float g_z[(size_t)N_TOK * LAT];
__device__ float g_h[(size_t)N_TOK * LAT];
__device__ float g_raw[(size_t)N_TOK * SYM];
__device__ float g_scores[(size_t)N_TOK * NC];
__device__ float g_cnorm[NC];
__device__ int   g_used[T_MSG];

// transposed weights [N, K] fp32
__device__ float g_wread_t[(size_t)LAT * 2 * LAT];
__device__ float g_wc1_t[(size_t)LAT * (LAT + SYM)];
__device__ float g_wc2_t[(size_t)LAT * LAT];
__device__ float g_wsym_t[(size_t)SYM * LAT];

// ---------------------------------------------------------------------------
// Helpers
// ---------------------------------------------------------------------------
__device__ __forceinline__ float tf32_rn(float x) {
    uint32_t u;
    asm("cvt.rna.tf32.f32 %0, %1;" : "=r"(u) : "f"(x));
    return __uint_as_float(u);
}
__device__ __forceinline__ uint32_t smem_u32(const void* p) {
    uint32_t a;
    asm("{ .reg .u64 t; cvta.to.shared.u64 t, %1; cvt.u32.u64 %0, t; }"
        : "=r"(a) : "l"(p));
    return a;
}
__device__ __forceinline__ void cp16(uint32_t dst, const void* src) {
    asm volatile("cp.async.cg.shared.global [%0], [%1], 16;"
                 :: "r"(dst), "l"(src));
}
#define CP_COMMIT() asm volatile("cp.async.commit_group;" ::: "memory")
#define CP_WAIT1()  asm volatile("cp.async.wait_group 1;" ::: "memory")

#define MMA8(d, a, b) \
    asm volatile( \
        "mma.sync.aligned.m16n8k8.row.col.f32.tf32.tf32.f32 " \
        "{%0,%1,%2,%3}, {%4,%5,%6,%7}, {%8,%9}, {%0,%1,%2,%3};" \
        : "+f"((d)[0]), "+f"((d)[1]), "+f"((d)[2]), "+f"((d)[3]) \
        : "r"((a)[0]), "r"((a)[1]), "r"((a)[2]), "r"((a)[3]), \
          "r"((b)[0]), "r"((b)[1]))

// ---------------------------------------------------------------------------
// tf32x3 mma.sync GEMM, fp32 staging + in-register split:
//   Out = alpha*(A @ B^T) + bias (+res)(relu)
// A = [A1|A2] along K (fp32 [M,K]); B fp32 [N,K].
// CTA tile 128x128, BK=32, 8 warps (4x2), warp tile 32x64.
// SMEM rows padded to 36 floats.
// ---------------------------------------------------------------------------
#define STG_F 9216                  // floats per stage: 2 arrays * 128*36
#define SMEM_BYTES (2 * STG_F * 4)  // 73728

template <bool RELU, bool HAS_RES>
__global__ __launch_bounds__(256, 1)
void tgemm_mma(const float* __restrict__ A1, const float* __restrict__ A2,
               int K1, int K,
               const float* __restrict__ B,
               const float* __restrict__ bias, float alpha,
               const float* __restrict__ residual,
               float* __restrict__ O, int Ntot) {
    extern __shared__ __align__(16) float smf[];
    const int tid = threadIdx.x;
    const int lane = tid & 31, wid = tid >> 5;
    const int wm = wid >> 1, wn = wid & 1;
    const int m0 = blockIdx.y << 7, n0 = blockIdx.x << 7;
    const uint32_t sbase = smem_u32(smf);

    float acc[2][8][4];
    #pragma unroll
    for (int mi = 0; mi < 2; mi++)
        #pragma unroll
        for (int ni = 0; ni < 8; ni++)
            #pragma unroll
            for (int r = 0; r < 4; r++) acc[mi][ni][r] = 0.f;

    const int nc = K >> 5;

    auto stage = [&](int s, int c) {
        const int k0 = c << 5;
        const uint32_t sb = sbase + (uint32_t)s * STG_F * 4;
        #pragma unroll
        for (int it = 0; it < 4; ++it) {
            int idx = tid + (it << 8);
            int row = idx >> 3, seg = idx & 7;
            int kk = k0 + (seg << 2);
            const float* p;
            if (kk < K1) p = A1 + (size_t)(m0 + row) * K1 + kk;
            else         p = A2 + (size_t)(m0 + row) * (K - K1) + (kk - K1);
            cp16(sb + (uint32_t)(row * 36 + (seg << 2)) * 4, p);
        }
        #pragma unroll
        for (int it = 0; it < 4; ++it) {
            int idx = tid + (it << 8);
            int row = idx >> 3, seg = idx & 7;
            cp16(sb + (uint32_t)(4608 + row * 36 + (seg << 2)) * 4,
                 B + (size_t)(n0 + row) * K + k0 + (seg << 2));
        }
    };

    stage(0, 0);
    CP_COMMIT();

    const int am = (wm << 5) + (lane >> 2);
    const int bn = (wn << 6) + (lane >> 2);
    const int kb = lane & 3;

    for (int c = 0; c < nc; ++c) {
        if (c + 1 < nc) stage((c + 1) & 1, c + 1);
        CP_COMMIT();
        CP_WAIT1();
        __syncthreads();

        const float* sA = smf + (c & 1) * STG_F;
        const float* sB = sA + 4608;

        #pragma unroll
        for (int k8 = 0; k8 < 4; ++k8) {
            const int ko = (k8 << 3) + kb;
            float av[2][4], bv[8][2];
            uint32_t ah[2][4], bh[8][2];
            #pragma unroll
            for (int mi = 0; mi < 2; mi++) {
                const float* p = sA + (am + (mi << 4)) * 36 + ko;
                av[mi][0] = p[0];   av[mi][1] = p[288];
                av[mi][2] = p[4];   av[mi][3] = p[292];
                #pragma unroll
                for (int r = 0; r < 4; r++)
                    ah[mi][r] = __float_as_uint(tf32_rn(av[mi][r]));
            }
            #pragma unroll
            for (int ni = 0; ni < 8; ni++) {
                const float* p = sB + (bn + (ni << 3)) * 36 + ko;
                bv[ni][0] = p[0];   bv[ni][1] = p[4];
                bh[ni][0] = __float_as_uint(tf32_rn(bv[ni][0]));
                bh[ni][1] = __float_as_uint(tf32_rn(bv[ni][1]));
            }
            // pass 1: hi * hi
            #pragma unroll
            for (int mi = 0; mi < 2; mi++)
                #pragma unroll
                for (int ni = 0; ni < 8; ni++) MMA8(acc[mi][ni], ah[mi], bh[ni]);
            // pass 2: hi * lo
            uint32_t bl[8][2];
            #pragma unroll
            for (int ni = 0; ni < 8; ni++) {
                bl[ni][0] = __float_as_uint(
                    tf32_rn(bv[ni][0] - __uint_as_float(bh[ni][0])));
                bl[ni][1] = __float_as_uint(
                    tf32_rn(bv[ni][1] - __uint_as_float(bh[ni][1])));
            }
            #pragma unroll
            for (int mi = 0; mi < 2; mi++)
                #pragma unroll
                for (int ni = 0; ni < 8; ni++) MMA8(acc[mi][ni], ah[mi], bl[ni]);
            // pass 3: lo * hi
            uint32_t al[2][4];
            #pragma unroll
            for (int mi = 0; mi < 2; mi++)
                #pragma unroll
                for (int r = 0; r < 4; r++)
                    al[mi][r] = __float_as_uint(
                        tf32_rn(av[mi][r] - __uint_as_float(ah[mi][r])));
            #pragma unroll
            for (int mi = 0; mi < 2; mi++)
                #pragma unroll
                for (int ni = 0; ni < 8; ni++) MMA8(acc[mi][ni], al[mi], bh[ni]);
        }
        __syncthreads();
    }

    // ---- epilogue ----
    #pragma unroll
    for (int mi = 0; mi < 2; mi++) {
        #pragma unroll
        for (int ni = 0; ni < 8; ni++) {
            int r = m0 + (wm << 5) + (mi << 4) + (lane >> 2);
            int nn = n0 + (wn << 6) + (ni << 3) + ((lane & 3) << 1);
            float b0 = bias[nn], b1 = bias[nn + 1];
            #pragma unroll
            for (int half = 0; half < 2; half++) {
                int rr = r + half * 8;
                float v0 = alpha * acc[mi][ni][half * 2 + 0] + b0;
                float v1 = alpha * acc[mi][ni][half * 2 + 1] + b1;
                if (HAS_RES) {
                    const float2 rv = *reinterpret_cast<const float2*>(
                        residual + (size_t)rr * Ntot + nn);
                    v0 += rv.x; v1 += rv.y;
                }
                if (RELU) { v0 = fmaxf(v0, 0.f); v1 = fmaxf(v1, 0.f); }
                *reinterpret_cast<float2*>(O + (size_t)rr * Ntot + nn) =
                    make_float2(v0, v1);
            }
        }
    }
}

// ---------------------------------------------------------------------------
// Prep / small kernels
// ---------------------------------------------------------------------------
__global__ void init_used_kernel() {
    if (threadIdx.x < T_MSG) g_used[threadIdx.x] = 0;
}

__global__ void routing_kernel(const float* __restrict__ bus_symbols,
                               const float* __restrict__ bus_outputs,
                               const float* __restrict__ Wq,
                               const float* __restrict__ bq) {
    int n = blockIdx.x;
    int tid = threadIdx.x;
    int lane = tid & 31, warp = tid >> 5;
    __shared__ float sWq[SYM];
    __shared__ float sRed[8];
    __shared__ int sTop;
    sWq[tid] = Wq[tid];
    __syncthreads();
    float best = -3.4e38f;
    int bt = 0;
    for (int t = 0; t < T_MSG; t++) {
        float v = bus_symbols[((size_t)t * N_TOK + n) * SYM + tid] * sWq[tid];
        #pragma unroll
        for (int off = 16; off > 0; off >>= 1)
            v += __shfl_down_sync(0xffffffffu, v, off);
        if (lane == 0) sRed[warp] = v;
        __syncthreads();
        if (tid == 0) {
            float r = sRed[0] + sRed[1] + sRed[2] + sRed[3]
                    + sRed[4] + sRed[5] + sRed[6] + sRed[7] + bq[0];
            if (r > best) { best = r; bt = t; }
        }
        __syncthreads();
    }
    if (tid == 0) { sTop = bt; atomicExch(&g_used[bt], 1); }
    __syncthreads();
    int top = sTop;
    const float4* src = reinterpret_cast<const float4*>(
        bus_outputs + ((size_t)top * N_TOK + n) * LAT);
    reinterpret_cast<float4*>(g_ctx + (size_t)n * LAT)[tid] = src[tid];
}

__global__ void keep_kernel(float* __restrict__ out_keep) {
    if (threadIdx.x < T_MSG)
        out_keep[threadIdx.x] = (g_used[threadIdx.x] == 0) ? 1.0f : 0.0f;
}

__global__ void cnorm_kernel(const float* __restrict__ codebook) {
    int c = blockIdx.x * (blockDim.x >> 5) + (threadIdx.x >> 5);
    int lane = threadIdx.x & 31;
    if (c >= NC) return;
    float s = 0.f;
    const float* row = codebook + (size_t)c * SYM;
    #pragma unroll
    for (int i = 0; i < SYM / 32; i++) {
        float v = row[lane + i * 32];
        s += v * v;
    }
    #pragma unroll
    for (int off = 16; off > 0; off >>= 1)
        s += __shfl_down_sync(0xffffffffu, s, off);
    if (lane == 0) g_cnorm[c] = s;
}

// transpose: W [K,N] -> [N,K]
__global__ void wprep_T(const float* __restrict__ W, int K, int N,
                        float* __restrict__ Wt) {
    __shared__ float t[32][33];
    int k0 = blockIdx.y << 5, n0 = blockIdx.x << 5;
    int tx = threadIdx.x, ty = threadIdx.y;
    #pragma unroll
    for (int i = 0; i < 32; i += 8)
        t[ty + i][tx] = W[(size_t)(k0 + ty + i) * N + n0 + tx];
    __syncthreads();
    #pragma unroll
    for (int i = 0; i < 32; i += 8)
        Wt[(size_t)(n0 + ty + i) * K + k0 + tx] = t[tx][ty + i];
}

__global__ void argmin_gather_kernel(const float* __restrict__ codebook,
                                     float* __restrict__ out_quant,
                                     float* __restrict__ out_idx) {
    int warp = threadIdx.x >> 5, lane = threadIdx.x & 31;
    int n = blockIdx.x * 8 + warp;
    const float* sc = g_scores + (size_t)n * NC;
    float best = 3.4e38f;
    int bi = 0;
    #pragma unroll
    for (int w = 0; w < NC / 32; w++) {
        int c = lane + w * 32;
        float v = sc[c];
        if (v < best) { best = v; bi = c; }
    }
    #pragma unroll
    for (int off = 16; off > 0; off >>= 1) {
        float ov = __shfl_xor_sync(0xffffffffu, best, off);
        int   oi = __shfl_xor_sync(0xffffffffu, bi, off);
        if (ov < best || (ov == best && oi < bi)) { best = ov; bi = oi; }
    }
    bi = __shfl_sync(0xffffffffu, bi, 0);
    if (lane == 0) out_idx[n] = (float)bi;
    const float* crow = codebook + (size_t)bi * SYM;
    float* qrow = out_quant + (size_t)n * SYM;
    #pragma unroll
    for (int j = 0; j < SYM / 32; j++) {
        int c = lane + j * 32;
        qrow[c] = crow[c];
    }
}

// ---------------------------------------------------------------------------
// Launch
// ---------------------------------------------------------------------------
extern "C" void kernel_launch(void* const* d_in, const int* in_sizes, int n_in,
                              void* d_out, int out_size) {
    const float* token_state = (const float*)d_in[0];
    const float* bus_symbols = (const float*)d_in[1];
    const float* bus_outputs = (const float*)d_in[3];
    const float* Wq    = (const float*)d_in[5];
    const float* bq    = (const float*)d_in[6];
    const float* Wread = (const float*)d_in[7];
    const float* bread = (const float*)d_in[8];
    const float* Wsym  = (const float*)d_in[9];
    const float* bsym  = (const float*)d_in[10];
    const float* Wc1   = (const float*)d_in[11];
    const float* bc1   = (const float*)d_in[12];
    const float* Wc2   = (const float*)d_in[13];
    const float* bc2   = (const float*)d_in[14];
    const float* codebook = (const float*)d_in[15];

    float* out = (float*)d_out;
    float* out_node  = out;
    float* out_quant = out + OUT_QUANT_OFF;
    float* out_idx   = out + OUT_IDX_OFF;
    float* out_keep  = out + OUT_KEEP_OFF;

    float *p_ctx, *p_z, *p_h, *p_raw, *p_scores, *p_cnorm;
    float *p_wrt, *p_w1t, *p_w2t, *p_wst;
    cudaGetSymbolAddress((void**)&p_ctx, g_ctx);
    cudaGetSymbolAddress((void**)&p_z, g_z);
    cudaGetSymbolAddress((void**)&p_h, g_h);
    cudaGetSymbolAddress((void**)&p_raw, g_raw);
    cudaGetSymbolAddress((void**)&p_scores, g_scores);
    cudaGetSymbolAddress((void**)&p_cnorm, g_cnorm);
    cudaGetSymbolAddress((void**)&p_wrt, g_wread_t);
    cudaGetSymbolAddress((void**)&p_w1t, g_wc1_t);
    cudaGetSymbolAddress((void**)&p_w2t, g_wc2_t);
    cudaGetSymbolAddress((void**)&p_wst, g_wsym_t);

    cudaFuncSetAttribute(tgemm_mma<false, false>,
                         cudaFuncAttributeMaxDynamicSharedMemorySize, SMEM_BYTES);
    cudaFuncSetAttribute(tgemm_mma<true, false>,
                         cudaFuncAttributeMaxDynamicSharedMemorySize, SMEM_BYTES);
    cudaFuncSetAttribute(tgemm_mma<false, true>,
                         cudaFuncAttributeMaxDynamicSharedMemorySize, SMEM_BYTES);

    dim3 tpb(32, 8);

    init_used_kernel<<<1, 32>>>();
    routing_kernel<<<N_TOK, 256>>>(bus_symbols, bus_outputs, Wq, bq);
    cnorm_kernel<<<NC / 8, 256>>>(codebook);

    wprep_T<<<dim3(LAT / 32, 2 * LAT / 32), tpb>>>(Wread, 2 * LAT, LAT, p_wrt);
    wprep_T<<<dim3(SYM / 32, LAT / 32), tpb>>>(Wsym, LAT, SYM, p_wst);
    wprep_T<<<dim3(LAT / 32, (LAT + SYM) / 32), tpb>>>(Wc1, LAT + SYM, LAT, p_w1t);
    wprep_T<<<dim3(LAT / 32, LAT / 32), tpb>>>(Wc2, LAT, LAT, p_w2t);

    // z = [ts | ctx] @ Wread + bread
    tgemm_mma<false, false><<<dim3(LAT / 128, N_TOK / 128), 256, SMEM_BYTES>>>(
        token_state, p_ctx, LAT, 2 * LAT, p_wrt, bread, 1.0f, nullptr, p_z, LAT);
    // raw = z @ Wsym + bsym
    tgemm_mma<false, false><<<dim3(SYM / 128, N_TOK / 128), 256, SMEM_BYTES>>>(
        p_z, p_z, LAT, LAT, p_wst, bsym, 1.0f, nullptr, p_raw, SYM);
    // scores = -2 * raw @ cb^T + ||c||^2
    tgemm_mma<false, false><<<dim3(NC / 128, N_TOK / 128), 256, SMEM_BYTES>>>(
        p_raw, p_raw, SYM, SYM, codebook, p_cnorm, -2.0f, nullptr, p_scores, NC);
    // argmin + quantized + indices
    argmin_gather_kernel<<<N_TOK / 8, 256>>>(codebook, out_quant, out_idx);
    // h = relu([z | quant] @ Wc1 + bc1)
    tgemm_mma<true, false><<<dim3(LAT / 128, N_TOK / 128), 256, SMEM_BYTES>>>(
        p_z, out_quant, LAT, LAT + SYM, p_w1t, bc1, 1.0f, nullptr, p_h, LAT);
    // node = h @ Wc2 + bc2 + token_state
    tgemm_mma<false, true><<<dim3(LAT / 128, N_TOK / 128), 256, SMEM_BYTES>>>(
        p_h, p_h, LAT, LAT, p_w2t, bc2, 1.0f, token_state, out_node, LAT);

    keep_kernel<<<1, 32>>>(out_keep);
}

// round 12
// speedup vs baseline: 1.5045x; 1.5045x over previous
#include <cuda_runtime.h>
#include <cuda_bf16.h>
#include <cstdint>

// ---------------------------------------------------------------------------
// Problem constants
// ---------------------------------------------------------------------------
#define T_MSG 8
#define N_TOK 8192
#define LAT 1024
#define SYM 256
#define NC 512

#define OUT_QUANT_OFF ((size_t)N_TOK * LAT)
#define OUT_IDX_OFF   (OUT_QUANT_OFF + (size_t)N_TOK * SYM)
#define OUT_KEEP_OFF  (OUT_IDX_OFF + (size_t)N_TOK)

// ---------------------------------------------------------------------------
// Device scratch (fp32 everywhere; bf16 split happens in registers)
// ---------------------------------------------------------------------------
__device__ float g_ctx[(size_t)N_TOK * LAT];
__device__ float g_z[(size_t)N_TOK * LAT];
__device__ float g_h[(size_t)N_TOK * LAT];
__device__ float g_raw[(size_t)N_TOK * SYM];
__device__ float g_scores[(size_t)N_TOK * NC];
__device__ float g_cnorm[NC];
__device__ int   g_used[T_MSG];

// transposed weights [N, K] fp32
__device__ float g_wread_t[(size_t)LAT * 2 * LAT];
__device__ float g_wc1_t[(size_t)LAT * (LAT + SYM)];
__device__ float g_wc2_t[(size_t)LAT * LAT];
__device__ float g_wsym_t[(size_t)SYM * LAT];

// ---------------------------------------------------------------------------
// Helpers
// ---------------------------------------------------------------------------
__device__ __forceinline__ uint32_t smem_u32(const void* p) {
    uint32_t a;
    asm("{ .reg .u64 t; cvta.to.shared.u64 t, %1; cvt.u32.u64 %0, t; }"
        : "=r"(a) : "l"(p));
    return a;
}
__device__ __forceinline__ void cp16(uint32_t dst, const void* src) {
    asm volatile("cp.async.cg.shared.global [%0], [%1], 16;"
                 :: "r"(dst), "l"(src));
}
#define CP_COMMIT() asm volatile("cp.async.commit_group;" ::: "memory")
#define CP_WAIT1()  asm volatile("cp.async.wait_group 1;" ::: "memory")

// bf16x3 split of a float2 (consecutive k pair): hi packed bf16x2 (lo half =
// v.x), mid = bf16(v - float(hi)) packed likewise.
__device__ __forceinline__ void bf16_split2(float2 v, uint32_t& hi, uint32_t& mid) {
    __nv_bfloat162 h = __float22bfloat162_rn(v);
    hi = *reinterpret_cast<uint32_t*>(&h);
    float hx = __uint_as_float(hi << 16);
    float hy = __uint_as_float(hi & 0xffff0000u);
    __nv_bfloat162 m = __float22bfloat162_rn(make_float2(v.x - hx, v.y - hy));
    mid = *reinterpret_cast<uint32_t*>(&m);
}

#define MMA16(d, a, b) \
    asm volatile( \
        "mma.sync.aligned.m16n8k16.row.col.f32.bf16.bf16.f32 " \
        "{%0,%1,%2,%3}, {%4,%5,%6,%7}, {%8,%9}, {%0,%1,%2,%3};" \
        : "+f"((d)[0]), "+f"((d)[1]), "+f"((d)[2]), "+f"((d)[3]) \
        : "r"((a)[0]), "r"((a)[1]), "r"((a)[2]), "r"((a)[3]), \
          "r"((b)[0]), "r"((b)[1]))

// ---------------------------------------------------------------------------
// bf16x3 mma.sync GEMM, fp32 staging + in-register split:
//   Out = alpha*(A @ B^T) + bias (+res)(relu)
// A = [A1|A2] along K (fp32 [M,K]); B fp32 [N,K].
// CTA tile 128x128, BK=32, 8 warps (4x2), warp tile 32x64.
// SMEM rows padded to 36 floats. m16n8k16 -> 96 MMAs/chunk (vs 192 tf32).
// ---------------------------------------------------------------------------
#define STG_F 9216                  // floats per stage: 2 arrays * 128*36
#define SMEM_BYTES (2 * STG_F * 4)  // 73728

template <bool RELU, bool HAS_RES>
__global__ __launch_bounds__(256, 1)
void tgemm_mma(const float* __restrict__ A1, const float* __restrict__ A2,
               int K1, int K,
               const float* __restrict__ B,
               const float* __restrict__ bias, float alpha,
               const float* __restrict__ residual,
               float* __restrict__ O, int Ntot) {
    extern __shared__ __align__(16) float smf[];
    const int tid = threadIdx.x;
    const int lane = tid & 31, wid = tid >> 5;
    const int wm = wid >> 1, wn = wid & 1;
    const int m0 = blockIdx.y << 7, n0 = blockIdx.x << 7;
    const uint32_t sbase = smem_u32(smf);

    float acc[2][8][4];
    #pragma unroll
    for (int mi = 0; mi < 2; mi++)
        #pragma unroll
        for (int ni = 0; ni < 8; ni++)
            #pragma unroll
            for (int r = 0; r < 4; r++) acc[mi][ni][r] = 0.f;

    const int nc = K >> 5;

    auto stage = [&](int s, int c) {
        const int k0 = c << 5;
        const uint32_t sb = sbase + (uint32_t)s * STG_F * 4;
        #pragma unroll
        for (int it = 0; it < 4; ++it) {
            int idx = tid + (it << 8);
            int row = idx >> 3, seg = idx & 7;
            int kk = k0 + (seg << 2);
            const float* p;
            if (kk < K1) p = A1 + (size_t)(m0 + row) * K1 + kk;
            else         p = A2 + (size_t)(m0 + row) * (K - K1) + (kk - K1);
            cp16(sb + (uint32_t)(row * 36 + (seg << 2)) * 4, p);
        }
        #pragma unroll
        for (int it = 0; it < 4; ++it) {
            int idx = tid + (it << 8);
            int row = idx >> 3, seg = idx & 7;
            cp16(sb + (uint32_t)(4608 + row * 36 + (seg << 2)) * 4,
                 B + (size_t)(n0 + row) * K + k0 + (seg << 2));
        }
    };

    stage(0, 0);
    CP_COMMIT();

    const int am = (wm << 5) + (lane >> 2);
    const int bn = (wn << 6) + (lane >> 2);

    for (int c = 0; c < nc; ++c) {
        if (c + 1 < nc) stage((c + 1) & 1, c + 1);
        CP_COMMIT();
        CP_WAIT1();
        __syncthreads();

        const float* sA = smf + (c & 1) * STG_F;
        const float* sB = sA + 4608;

        #pragma unroll
        for (int kk = 0; kk < 2; ++kk) {          // two k16 blocks per BK=32
            const int ko = (kk << 4) + ((lane & 3) << 1);
            uint32_t ah[2][4], al[2][4], bh[8][2], bl[8][2];
            #pragma unroll
            for (int mi = 0; mi < 2; mi++) {
                const float* p = sA + (am + (mi << 4)) * 36 + ko;
                float2 v0 = *reinterpret_cast<const float2*>(p);        // row, k
                float2 v1 = *reinterpret_cast<const float2*>(p + 288);  // row+8
                float2 v2 = *reinterpret_cast<const float2*>(p + 8);    // k+8
                float2 v3 = *reinterpret_cast<const float2*>(p + 296);
                bf16_split2(v0, ah[mi][0], al[mi][0]);
                bf16_split2(v1, ah[mi][1], al[mi][1]);
                bf16_split2(v2, ah[mi][2], al[mi][2]);
                bf16_split2(v3, ah[mi][3], al[mi][3]);
            }
            #pragma unroll
            for (int ni = 0; ni < 8; ni++) {
                const float* p = sB + (bn + (ni << 3)) * 36 + ko;
                float2 v0 = *reinterpret_cast<const float2*>(p);
                float2 v1 = *reinterpret_cast<const float2*>(p + 8);
                bf16_split2(v0, bh[ni][0], bl[ni][0]);
                bf16_split2(v1, bh[ni][1], bl[ni][1]);
            }
            // pass 1: hi * hi
            #pragma unroll
            for (int mi = 0; mi < 2; mi++)
                #pragma unroll
                for (int ni = 0; ni < 8; ni++) MMA16(acc[mi][ni], ah[mi], bh[ni]);
            // pass 2: hi * mid
            #pragma unroll
            for (int mi = 0; mi < 2; mi++)
                #pragma unroll
                for (int ni = 0; ni < 8; ni++) MMA16(acc[mi][ni], ah[mi], bl[ni]);
            // pass 3: mid * hi
            #pragma unroll
            for (int mi = 0; mi < 2; mi++)
                #pragma unroll
                for (int ni = 0; ni < 8; ni++) MMA16(acc[mi][ni], al[mi], bh[ni]);
        }
        __syncthreads();
    }

    // ---- epilogue (accumulator layout identical to m16n8k8) ----
    #pragma unroll
    for (int mi = 0; mi < 2; mi++) {
        #pragma unroll
        for (int ni = 0; ni < 8; ni++) {
            int r = m0 + (wm << 5) + (mi << 4) + (lane >> 2);
            int nn = n0 + (wn << 6) + (ni << 3) + ((lane & 3) << 1);
            float b0 = bias[nn], b1 = bias[nn + 1];
            #pragma unroll
            for (int half = 0; half < 2; half++) {
                int rr = r + half * 8;
                float v0 = alpha * acc[mi][ni][half * 2 + 0] + b0;
                float v1 = alpha * acc[mi][ni][half * 2 + 1] + b1;
                if (HAS_RES) {
                    const float2 rv = *reinterpret_cast<const float2*>(
                        residual + (size_t)rr * Ntot + nn);
                    v0 += rv.x; v1 += rv.y;
                }
                if (RELU) { v0 = fmaxf(v0, 0.f); v1 = fmaxf(v1, 0.f); }
                *reinterpret_cast<float2*>(O + (size_t)rr * Ntot + nn) =
                    make_float2(v0, v1);
            }
        }
    }
}

// ---------------------------------------------------------------------------
// Prep / small kernels
// ---------------------------------------------------------------------------
__global__ void init_used_kernel() {
    if (threadIdx.x < T_MSG) g_used[threadIdx.x] = 0;
}

__global__ void routing_kernel(const float* __restrict__ bus_symbols,
                               const float* __restrict__ bus_outputs,
                               const float* __restrict__ Wq,
                               const float* __restrict__ bq) {
    int n = blockIdx.x;
    int tid = threadIdx.x;
    int lane = tid & 31, warp = tid >> 5;
    __shared__ float sWq[SYM];
    __shared__ float sRed[8];
    __shared__ int sTop;
    sWq[tid] = Wq[tid];
    __syncthreads();
    float best = -3.4e38f;
    int bt = 0;
    for (int t = 0; t < T_MSG; t++) {
        float v = bus_symbols[((size_t)t * N_TOK + n) * SYM + tid] * sWq[tid];
        #pragma unroll
        for (int off = 16; off > 0; off >>= 1)
            v += __shfl_down_sync(0xffffffffu, v, off);
        if (lane == 0) sRed[warp] = v;
        __syncthreads();
        if (tid == 0) {
            float r = sRed[0] + sRed[1] + sRed[2] + sRed[3]
                    + sRed[4] + sRed[5] + sRed[6] + sRed[7] + bq[0];
            if (r > best) { best = r; bt = t; }
        }
        __syncthreads();
    }
    if (tid == 0) { sTop = bt; atomicExch(&g_used[bt], 1); }
    __syncthreads();
    int top = sTop;
    const float4* src = reinterpret_cast<const float4*>(
        bus_outputs + ((size_t)top * N_TOK + n) * LAT);
    reinterpret_cast<float4*>(g_ctx + (size_t)n * LAT)[tid] = src[tid];
}

__global__ void keep_kernel(float* __restrict__ out_keep) {
    if (threadIdx.x < T_MSG)
        out_keep[threadIdx.x] = (g_used[threadIdx.x] == 0) ? 1.0f : 0.0f;
}

__global__ void cnorm_kernel(const float* __restrict__ codebook) {
    int c = blockIdx.x * (blockDim.x >> 5) + (threadIdx.x >> 5);
    int lane = threadIdx.x & 31;
    if (c >= NC) return;
    float s = 0.f;
    const float* row = codebook + (size_t)c * SYM;
    #pragma unroll
    for (int i = 0; i < SYM / 32; i++) {
        float v = row[lane + i * 32];
        s += v * v;
    }
    #pragma unroll
    for (int off = 16; off > 0; off >>= 1)
        s += __shfl_down_sync(0xffffffffu, s, off);
    if (lane == 0) g_cnorm[c] = s;
}

// transpose: W [K,N] -> [N,K]
__global__ void wprep_T(const float* __restrict__ W, int K, int N,
                        float* __restrict__ Wt) {
    __shared__ float t[32][33];
    int k0 = blockIdx.y << 5, n0 = blockIdx.x << 5;
    int tx = threadIdx.x, ty = threadIdx.y;
    #pragma unroll
    for (int i = 0; i < 32; i += 8)
        t[ty + i][tx] = W[(size_t)(k0 + ty + i) * N + n0 + tx];
    __syncthreads();
    #pragma unroll
    for (int i = 0; i < 32; i += 8)
        Wt[(size_t)(n0 + ty + i) * K + k0 + tx] = t[tx][ty + i];
}

__global__ void argmin_gather_kernel(const float* __restrict__ codebook,
                                     float* __restrict__ out_quant,
                                     float* __restrict__ out_idx) {
    int warp = threadIdx.x >> 5, lane = threadIdx.x & 31;
    int n = blockIdx.x * 8 + warp;
    const float* sc = g_scores + (size_t)n * NC;
    float best = 3.4e38f;
    int bi = 0;
    #pragma unroll
    for (int w = 0; w < NC / 32; w++) {
        int c = lane + w * 32;
        float v = sc[c];
        if (v < best) { best = v; bi = c; }
    }
    #pragma unroll
    for (int off = 16; off > 0; off >>= 1) {
        float ov = __shfl_xor_sync(0xffffffffu, best, off);
        int   oi = __shfl_xor_sync(0xffffffffu, bi, off);
        if (ov < best || (ov == best && oi < bi)) { best = ov; bi = oi; }
    }
    bi = __shfl_sync(0xffffffffu, bi, 0);
    if (lane == 0) out_idx[n] = (float)bi;
    const float* crow = codebook + (size_t)bi * SYM;
    float* qrow = out_quant + (size_t)n * SYM;
    #pragma unroll
    for (int j = 0; j < SYM / 32; j++) {
        int c = lane + j * 32;
        qrow[c] = crow[c];
    }
}

// ---------------------------------------------------------------------------
// Launch
// ---------------------------------------------------------------------------
extern "C" void kernel_launch(void* const* d_in, const int* in_sizes, int n_in,
                              void* d_out, int out_size) {
    const float* token_state = (const float*)d_in[0];
    const float* bus_symbols = (const float*)d_in[1];
    const float* bus_outputs = (const float*)d_in[3];
    const float* Wq    = (const float*)d_in[5];
    const float* bq    = (const float*)d_in[6];
    const float* Wread = (const float*)d_in[7];
    const float* bread = (const float*)d_in[8];
    const float* Wsym  = (const float*)d_in[9];
    const float* bsym  = (const float*)d_in[10];
    const float* Wc1   = (const float*)d_in[11];
    const float* bc1   = (const float*)d_in[12];
    const float* Wc2   = (const float*)d_in[13];
    const float* bc2   = (const float*)d_in[14];
    const float* codebook = (const float*)d_in[15];

    float* out = (float*)d_out;
    float* out_node  = out;
    float* out_quant = out + OUT_QUANT_OFF;
    float* out_idx   = out + OUT_IDX_OFF;
    float* out_keep  = out + OUT_KEEP_OFF;

    float *p_ctx, *p_z, *p_h, *p_raw, *p_scores, *p_cnorm;
    float *p_wrt, *p_w1t, *p_w2t, *p_wst;
    cudaGetSymbolAddress((void**)&p_ctx, g_ctx);
    cudaGetSymbolAddress((void**)&p_z, g_z);
    cudaGetSymbolAddress((void**)&p_h, g_h);
    cudaGetSymbolAddress((void**)&p_raw, g_raw);
    cudaGetSymbolAddress((void**)&p_scores, g_scores);
    cudaGetSymbolAddress((void**)&p_cnorm, g_cnorm);
    cudaGetSymbolAddress((void**)&p_wrt, g_wread_t);
    cudaGetSymbolAddress((void**)&p_w1t, g_wc1_t);
    cudaGetSymbolAddress((void**)&p_w2t, g_wc2_t);
    cudaGetSymbolAddress((void**)&p_wst, g_wsym_t);

    cudaFuncSetAttribute(tgemm_mma<false, false>,
                         cudaFuncAttributeMaxDynamicSharedMemorySize, SMEM_BYTES);
    cudaFuncSetAttribute(tgemm_mma<true, false>,
                         cudaFuncAttributeMaxDynamicSharedMemorySize, SMEM_BYTES);
    cudaFuncSetAttribute(tgemm_mma<false, true>,
                         cudaFuncAttributeMaxDynamicSharedMemorySize, SMEM_BYTES);

    dim3 tpb(32, 8);

    init_used_kernel<<<1, 32>>>();
    routing_kernel<<<N_TOK, 256>>>(bus_symbols, bus_outputs, Wq, bq);
    cnorm_kernel<<<NC / 8, 256>>>(codebook);

    wprep_T<<<dim3(LAT / 32, 2 * LAT / 32), tpb>>>(Wread, 2 * LAT, LAT, p_wrt);
    wprep_T<<<dim3(SYM / 32, LAT / 32), tpb>>>(Wsym, LAT, SYM, p_wst);
    wprep_T<<<dim3(LAT / 32, (LAT + SYM) / 32), tpb>>>(Wc1, LAT + SYM, LAT, p_w1t);
    wprep_T<<<dim3(LAT / 32, LAT / 32), tpb>>>(Wc2, LAT, LAT, p_w2t);

    // z = [ts | ctx] @ Wread + bread
    tgemm_mma<false, false><<<dim3(LAT / 128, N_TOK / 128), 256, SMEM_BYTES>>>(
        token_state, p_ctx, LAT, 2 * LAT, p_wrt, bread, 1.0f, nullptr, p_z, LAT);
    // raw = z @ Wsym + bsym
    tgemm_mma<false, false><<<dim3(SYM / 128, N_TOK / 128), 256, SMEM_BYTES>>>(
        p_z, p_z, LAT, LAT, p_wst, bsym, 1.0f, nullptr, p_raw, SYM);
    // scores = -2 * raw @ cb^T + ||c||^2
    tgemm_mma<false, false><<<dim3(NC / 128, N_TOK / 128), 256, SMEM_BYTES>>>(
        p_raw, p_raw, SYM, SYM, codebook, p_cnorm, -2.0f, nullptr, p_scores, NC);
    // argmin + quantized + indices
    argmin_gather_kernel<<<N_TOK / 8, 256>>>(codebook, out_quant, out_idx);
    // h = relu([z | quant] @ Wc1 + bc1)
    tgemm_mma<true, false><<<dim3(LAT / 128, N_TOK / 128), 256, SMEM_BYTES>>>(
        p_z, out_quant, LAT, LAT + SYM, p_w1t, bc1, 1.0f, nullptr, p_h, LAT);
    // node = h @ Wc2 + bc2 + token_state
    tgemm_mma<false, true><<<dim3(LAT / 128, N_TOK / 128), 256, SMEM_BYTES>>>(
        p_h, p_h, LAT, LAT, p_w2t, bc2, 1.0f, token_state, out_node, LAT);

    keep_kernel<<<1, 32>>>(out_keep);
}

// round 14
// speedup vs baseline: 1.5998x; 1.0633x over previous
#include <cuda_runtime.h>
#include <cuda_bf16.h>
#include <cstdint>

// ---------------------------------------------------------------------------
// Problem constants
// ---------------------------------------------------------------------------
#define T_MSG 8
#define N_TOK 8192
#define LAT 1024
#define SYM 256
#define NC 512

#define OUT_QUANT_OFF ((size_t)N_TOK * LAT)
#define OUT_IDX_OFF   (OUT_QUANT_OFF + (size_t)N_TOK * SYM)
#define OUT_KEEP_OFF  (OUT_IDX_OFF + (size_t)N_TOK)

// ---------------------------------------------------------------------------
// Device scratch — all GEMM operands pre-split to bf16 hi/lo pairs
// ---------------------------------------------------------------------------
__device__ uint16_t g_ts_h[(size_t)N_TOK * LAT];
__device__ uint16_t g_ts_l[(size_t)N_TOK * LAT];
__device__ uint16_t g_ctx_h[(size_t)N_TOK * LAT];
__device__ uint16_t g_ctx_l[(size_t)N_TOK * LAT];
__device__ uint16_t g_z_h[(size_t)N_TOK * LAT];
__device__ uint16_t g_z_l[(size_t)N_TOK * LAT];
__device__ uint16_t g_h_h[(size_t)N_TOK * LAT];
__device__ uint16_t g_h_l[(size_t)N_TOK * LAT];
__device__ uint16_t g_raw_h[(size_t)N_TOK * SYM];
__device__ uint16_t g_raw_l[(size_t)N_TOK * SYM];
__device__ uint16_t g_q_h[(size_t)N_TOK * SYM];
__device__ uint16_t g_q_l[(size_t)N_TOK * SYM];
__device__ uint16_t g_cb_h[(size_t)NC * SYM];
__device__ uint16_t g_cb_l[(size_t)NC * SYM];

__device__ uint16_t g_wr_h[(size_t)LAT * 2 * LAT];
__device__ uint16_t g_wr_l[(size_t)LAT * 2 * LAT];
__device__ uint16_t g_w1_h[(size_t)LAT * (LAT + SYM)];
__device__ uint16_t g_w1_l[(size_t)LAT * (LAT + SYM)];
__device__ uint16_t g_w2_h[(size_t)LAT * LAT];
__device__ uint16_t g_w2_l[(size_t)LAT * LAT];
__device__ uint16_t g_ws_h[(size_t)SYM * LAT];
__device__ uint16_t g_ws_l[(size_t)SYM * LAT];

__device__ float g_scores[(size_t)N_TOK * NC];
__device__ float g_cnorm[NC];
__device__ int   g_used[T_MSG];

// ---------------------------------------------------------------------------
// Helpers
// ---------------------------------------------------------------------------
__device__ __forceinline__ uint32_t smem_u32(const void* p) {
    uint32_t a;
    asm("{ .reg .u64 t; cvta.to.shared.u64 t, %1; cvt.u32.u64 %0, t; }"
        : "=r"(a) : "l"(p));
    return a;
}
__device__ __forceinline__ void cp16(uint32_t dst, const void* src) {
    asm volatile("cp.async.cg.shared.global [%0], [%1], 16;"
                 :: "r"(dst), "l"(src));
}
#define CP_COMMIT() asm volatile("cp.async.commit_group;" ::: "memory")
#define CP_WAIT1()  asm volatile("cp.async.wait_group 1;" ::: "memory")

// bf16 split of a float2: hi = bf16x2(v), lo = bf16x2(v - float(hi))
__device__ __forceinline__ void bf16_split2(float2 v, uint32_t& hi, uint32_t& lo) {
    __nv_bfloat162 h = __float22bfloat162_rn(v);
    hi = *reinterpret_cast<uint32_t*>(&h);
    float hx = __uint_as_float(hi << 16);
    float hy = __uint_as_float(hi & 0xffff0000u);
    __nv_bfloat162 m = __float22bfloat162_rn(make_float2(v.x - hx, v.y - hy));
    lo = *reinterpret_cast<uint32_t*>(&m);
}
__device__ __forceinline__ void bf16_split1(float v, uint16_t& hi, uint16_t& lo) {
    __nv_bfloat16 h = __float2bfloat16_rn(v);
    hi = *reinterpret_cast<uint16_t*>(&h);
    float hf = __uint_as_float(((uint32_t)hi) << 16);
    __nv_bfloat16 m = __float2bfloat16_rn(v - hf);
    lo = *reinterpret_cast<uint16_t*>(&m);
}

#define MMA16(d, a, b) \
    asm volatile( \
        "mma.sync.aligned.m16n8k16.row.col.f32.bf16.bf16.f32 " \
        "{%0,%1,%2,%3}, {%4,%5,%6,%7}, {%8,%9}, {%0,%1,%2,%3};" \
        : "+f"((d)[0]), "+f"((d)[1]), "+f"((d)[2]), "+f"((d)[3]) \
        : "r"((a)[0]), "r"((a)[1]), "r"((a)[2]), "r"((a)[3]), \
          "r"((b)[0]), "r"((b)[1]))

// ---------------------------------------------------------------------------
// bf16x3 mma.sync GEMM on pre-split operands:
//   Out = alpha*(A @ B^T) + bias (+res)(relu)
// A = [A1|A2] along K (bf16 hi/lo [M,K]); B bf16 hi/lo [N,K].
// CTA tile 128x128, BK=32, 8 warps (4x2), warp tile 32x64.
// SMEM: 4 arrays/stage, rows 128 x 80B (32 bf16 + pad) - conflict-free.
// Mainloop is pure LDS.32 + MMA (zero conversion math).
// ---------------------------------------------------------------------------
#define STG_B 40960                  // bytes per stage: 4 arrays * 128*80
#define SMEM_BYTES (2 * STG_B)       // 81920

template <bool SPLIT, bool RELU, bool HAS_RES>
__global__ __launch_bounds__(256, 1)
void tgemm_mma(const uint16_t* __restrict__ A1h, const uint16_t* __restrict__ A1l,
               const uint16_t* __restrict__ A2h, const uint16_t* __restrict__ A2l,
               int K1, int K,
               const uint16_t* __restrict__ Bh, const uint16_t* __restrict__ Bl,
               const float* __restrict__ bias, float alpha,
               const float* __restrict__ residual,
               float* __restrict__ Ofp,
               uint16_t* __restrict__ Oh, uint16_t* __restrict__ Ol,
               int Ntot) {
    extern __shared__ __align__(16) char smc[];
    const int tid = threadIdx.x;
    const int lane = tid & 31, wid = tid >> 5;
    const int wm = wid >> 1, wn = wid & 1;
    const int m0 = blockIdx.y << 7, n0 = blockIdx.x << 7;
    const uint32_t sbase = smem_u32(smc);

    float acc[2][8][4];
    #pragma unroll
    for (int mi = 0; mi < 2; mi++)
        #pragma unroll
        for (int ni = 0; ni < 8; ni++)
            #pragma unroll
            for (int r = 0; r < 4; r++) acc[mi][ni][r] = 0.f;

    const int nc = K >> 5;

    auto stage = [&](int s, int c) {
        const int k0 = c << 5;
        const uint32_t sb = sbase + (uint32_t)s * STG_B;
        #pragma unroll
        for (int it = 0; it < 2; ++it) {
            int idx = tid + (it << 8);         // 0..511
            int row = idx >> 2, seg = idx & 3; // 4 x 16B segs per 64B row
            int kk = k0 + (seg << 3);
            const uint16_t *ph, *pl;
            if (kk < K1) {
                size_t o = (size_t)(m0 + row) * K1 + kk;
                ph = A1h + o; pl = A1l + o;
            } else {
                size_t o = (size_t)(m0 + row) * (K - K1) + (kk - K1);
                ph = A2h + o; pl = A2l + o;
            }
            uint32_t d = sb + (uint32_t)(row * 80 + (seg << 4));
            cp16(d, ph);
            cp16(d + 10240, pl);
        }
        #pragma unroll
        for (int it = 0; it < 2; ++it) {
            int idx = tid + (it << 8);
            int row = idx >> 2, seg = idx & 3;
            size_t o = (size_t)(n0 + row) * K + k0 + (seg << 3);
            uint32_t d = sb + 20480u + (uint32_t)(row * 80 + (seg << 4));
            cp16(d, Bh + o);
            cp16(d + 10240, Bl + o);
        }
    };

    stage(0, 0);
    CP_COMMIT();

    const int am = (wm << 5) + (lane >> 2);
    const int bn = (wn << 6) + (lane >> 2);

    for (int c = 0; c < nc; ++c) {
        if (c + 1 < nc) stage((c + 1) & 1, c + 1);
        CP_COMMIT();
        CP_WAIT1();
        __syncthreads();

        const char* base = smc + (c & 1) * STG_B;
        const char* sAh = base;
        const char* sAl = base + 10240;
        const char* sBh = base + 20480;
        const char* sBl = base + 30720;

        #pragma unroll
        for (int kk = 0; kk < 2; ++kk) {       // two k16 blocks per BK=32
            const int kbyte = (kk << 5) + ((lane & 3) << 2);
            uint32_t ah[2][4], al[2][4], bh[8][2], bl[8][2];
            #pragma unroll
            for (int mi = 0; mi < 2; mi++) {
                int ro = (am + (mi << 4)) * 80 + kbyte;
                ah[mi][0] = *reinterpret_cast<const uint32_t*>(sAh + ro);
                ah[mi][1] = *reinterpret_cast<const uint32_t*>(sAh + ro + 640);
                ah[mi][2] = *reinterpret_cast<const uint32_t*>(sAh + ro + 16);
                ah[mi][3] = *reinterpret_cast<const uint32_t*>(sAh + ro + 656);
                al[mi][0] = *reinterpret_cast<const uint32_t*>(sAl + ro);
                al[mi][1] = *reinterpret_cast<const uint32_t*>(sAl + ro + 640);
                al[mi][2] = *reinterpret_cast<const uint32_t*>(sAl + ro + 16);
                al[mi][3] = *reinterpret_cast<const uint32_t*>(sAl + ro + 656);
            }
            #pragma unroll
            for (int ni = 0; ni < 8; ni++) {
                int ro = (bn + (ni << 3)) * 80 + kbyte;
                bh[ni][0] = *reinterpret_cast<const uint32_t*>(sBh + ro);
                bh[ni][1] = *reinterpret_cast<const uint32_t*>(sBh + ro + 16);
                bl[ni][0] = *reinterpret_cast<const uint32_t*>(sBl + ro);
                bl[ni][1] = *reinterpret_cast<const uint32_t*>(sBl + ro + 16);
            }
            // pass 1: hi * hi
            #pragma unroll
            for (int mi = 0; mi < 2; mi++)
                #pragma unroll
                for (int ni = 0; ni < 8; ni++) MMA16(acc[mi][ni], ah[mi], bh[ni]);
            // pass 2: hi * lo
            #pragma unroll
            for (int mi = 0; mi < 2; mi++)
                #pragma unroll
                for (int ni = 0; ni < 8; ni++) MMA16(acc[mi][ni], ah[mi], bl[ni]);
            // pass 3: lo * hi
            #pragma unroll
            for (int mi = 0; mi < 2; mi++)
                #pragma unroll
                for (int ni = 0; ni < 8; ni++) MMA16(acc[mi][ni], al[mi], bh[ni]);
        }
        __syncthreads();
    }

    // ---- epilogue ----
    #pragma unroll
    for (int mi = 0; mi < 2; mi++) {
        #pragma unroll
        for (int ni = 0; ni < 8; ni++) {
            int r = m0 + (wm << 5) + (mi << 4) + (lane >> 2);
            int nn = n0 + (wn << 6) + (ni << 3) + ((lane & 3) << 1);
            float b0 = bias[nn], b1 = bias[nn + 1];
            #pragma unroll
            for (int half = 0; half < 2; half++) {
                int rr = r + half * 8;
                float v0 = alpha * acc[mi][ni][half * 2 + 0] + b0;
                float v1 = alpha * acc[mi][ni][half * 2 + 1] + b1;
                if (HAS_RES) {
                    const float2 rv = *reinterpret_cast<const float2*>(
                        residual + (size_t)rr * Ntot + nn);
                    v0 += rv.x; v1 += rv.y;
                }
                if (RELU) { v0 = fmaxf(v0, 0.f); v1 = fmaxf(v1, 0.f); }
                if (SPLIT) {
                    uint32_t h, l;
                    bf16_split2(make_float2(v0, v1), h, l);
                    *reinterpret_cast<uint32_t*>(Oh + (size_t)rr * Ntot + nn) = h;
                    *reinterpret_cast<uint32_t*>(Ol + (size_t)rr * Ntot + nn) = l;
                } else {
                    *reinterpret_cast<float2*>(Ofp + (size_t)rr * Ntot + nn) =
                        make_float2(v0, v1);
                }
            }
        }
    }
}

// ---------------------------------------------------------------------------
// Prep / small kernels
// ---------------------------------------------------------------------------
__global__ void init_used_kernel() {
    if (threadIdx.x < T_MSG) g_used[threadIdx.x] = 0;
}

// elementwise fp32 -> bf16 hi/lo (float4 per thread)
__global__ void split_bf16_kernel(const float* __restrict__ in,
                                  uint16_t* __restrict__ hi,
                                  uint16_t* __restrict__ lo) {
    int i = blockIdx.x * 256 + threadIdx.x;
    float4 v = reinterpret_cast<const float4*>(in)[i];
    uint32_t h0, l0, h1, l1;
    bf16_split2(make_float2(v.x, v.y), h0, l0);
    bf16_split2(make_float2(v.z, v.w), h1, l1);
    reinterpret_cast<uint2*>(hi)[i] = make_uint2(h0, h1);
    reinterpret_cast<uint2*>(lo)[i] = make_uint2(l0, l1);
}

__global__ void routing_kernel(const float* __restrict__ bus_symbols,
                               const float* __restrict__ bus_outputs,
                               const float* __restrict__ Wq,
                               const float* __restrict__ bq) {
    int n = blockIdx.x;
    int tid = threadIdx.x;
    int lane = tid & 31, warp = tid >> 5;
    __shared__ float sWq[SYM];
    __shared__ float sRed[8];
    __shared__ int sTop;
    sWq[tid] = Wq[tid];
    __syncthreads();
    float best = -3.4e38f;
    int bt = 0;
    for (int t = 0; t < T_MSG; t++) {
        float v = bus_symbols[((size_t)t * N_TOK + n) * SYM + tid] * sWq[tid];
        #pragma unroll
        for (int off = 16; off > 0; off >>= 1)
            v += __shfl_down_sync(0xffffffffu, v, off);
        if (lane == 0) sRed[warp] = v;
        __syncthreads();
        if (tid == 0) {
            float r = sRed[0] + sRed[1] + sRed[2] + sRed[3]
                    + sRed[4] + sRed[5] + sRed[6] + sRed[7] + bq[0];
            if (r > best) { best = r; bt = t; }
        }
        __syncthreads();
    }
    if (tid == 0) { sTop = bt; atomicExch(&g_used[bt], 1); }
    __syncthreads();
    int top = sTop;
    float4 v = reinterpret_cast<const float4*>(
        bus_outputs + ((size_t)top * N_TOK + n) * LAT)[tid];
    uint32_t h0, l0, h1, l1;
    bf16_split2(make_float2(v.x, v.y), h0, l0);
    bf16_split2(make_float2(v.z, v.w), h1, l1);
    size_t off = (size_t)n * LAT;
    reinterpret_cast<uint2*>(g_ctx_h + off)[tid] = make_uint2(h0, h1);
    reinterpret_cast<uint2*>(g_ctx_l + off)[tid] = make_uint2(l0, l1);
}

__global__ void keep_kernel(float* __restrict__ out_keep) {
    if (threadIdx.x < T_MSG)
        out_keep[threadIdx.x] = (g_used[threadIdx.x] == 0) ? 1.0f : 0.0f;
}

__global__ void cnorm_kernel(const float* __restrict__ codebook) {
    int c = blockIdx.x * (blockDim.x >> 5) + (threadIdx.x >> 5);
    int lane = threadIdx.x & 31;
    if (c >= NC) return;
    float s = 0.f;
    const float* row = codebook + (size_t)c * SYM;
    #pragma unroll
    for (int i = 0; i < SYM / 32; i++) {
        float v = row[lane + i * 32];
        s += v * v;
    }
    #pragma unroll
    for (int off = 16; off > 0; off >>= 1)
        s += __shfl_down_sync(0xffffffffu, s, off);
    if (lane == 0) g_cnorm[c] = s;
}

// transpose + bf16 split: W [K,N] fp32 -> hi/lo [N,K] bf16
__global__ void wprep_T(const float* __restrict__ W, int K, int N,
                        uint16_t* __restrict__ Wh, uint16_t* __restrict__ Wl) {
    __shared__ float t[32][33];
    int k0 = blockIdx.y << 5, n0 = blockIdx.x << 5;
    int tx = threadIdx.x, ty = threadIdx.y;
    #pragma unroll
    for (int i = 0; i < 32; i += 8)
        t[ty + i][tx] = W[(size_t)(k0 + ty + i) * N + n0 + tx];
    __syncthreads();
    #pragma unroll
    for (int i = 0; i < 32; i += 8) {
        float v = t[tx][ty + i];
        uint16_t h, l;
        bf16_split1(v, h, l);
        size_t o = (size_t)(n0 + ty + i) * K + k0 + tx;
        Wh[o] = h;
        Wl[o] = l;
    }
}

__global__ void argmin_gather_kernel(const float* __restrict__ codebook,
                                     float* __restrict__ out_quant,
                                     float* __restrict__ out_idx) {
    int warp = threadIdx.x >> 5, lane = threadIdx.x & 31;
    int n = blockIdx.x * 8 + warp;
    const float* sc = g_scores + (size_t)n * NC;
    float best = 3.4e38f;
    int bi = 0;
    #pragma unroll
    for (int w = 0; w < NC / 32; w++) {
        int c = lane + w * 32;
        float v = sc[c];
        if (v < best) { best = v; bi = c; }
    }
    #pragma unroll
    for (int off = 16; off > 0; off >>= 1) {
        float ov = __shfl_xor_sync(0xffffffffu, best, off);
        int   oi = __shfl_xor_sync(0xffffffffu, bi, off);
        if (ov < best || (ov == best && oi < bi)) { best = ov; bi = oi; }
    }
    bi = __shfl_sync(0xffffffffu, bi, 0);
    if (lane == 0) out_idx[n] = (float)bi;
    const float* crow = codebook + (size_t)bi * SYM;
    const uint16_t* ch = g_cb_h + (size_t)bi * SYM;
    const uint16_t* cl = g_cb_l + (size_t)bi * SYM;
    float* qrow = out_quant + (size_t)n * SYM;
    uint16_t* qh = g_q_h + (size_t)n * SYM;
    uint16_t* ql = g_q_l + (size_t)n * SYM;
    #pragma unroll
    for (int j = 0; j < SYM / 32; j++) {
        int c = lane + j * 32;
        qrow[c] = crow[c];
        qh[c] = ch[c];
        ql[c] = cl[c];
    }
}

// ---------------------------------------------------------------------------
// Launch
// ---------------------------------------------------------------------------
extern "C" void kernel_launch(void* const* d_in, const int* in_sizes, int n_in,
                              void* d_out, int out_size) {
    const float* token_state = (const float*)d_in[0];
    const float* bus_symbols = (const float*)d_in[1];
    const float* bus_outputs = (const float*)d_in[3];
    const float* Wq    = (const float*)d_in[5];
    const float* bq    = (const float*)d_in[6];
    const float* Wread = (const float*)d_in[7];
    const float* bread = (const float*)d_in[8];
    const float* Wsym  = (const float*)d_in[9];
    const float* bsym  = (const float*)d_in[10];
    const float* Wc1   = (const float*)d_in[11];
    const float* bc1   = (const float*)d_in[12];
    const float* Wc2   = (const float*)d_in[13];
    const float* bc2   = (const float*)d_in[14];
    const float* codebook = (const float*)d_in[15];

    float* out = (float*)d_out;
    float* out_node  = out;
    float* out_quant = out + OUT_QUANT_OFF;
    float* out_idx   = out + OUT_IDX_OFF;
    float* out_keep  = out + OUT_KEEP_OFF;

    #define SA(p, s) cudaGetSymbolAddress((void**)&p, s)
    uint16_t *p_tsh, *p_tsl, *p_ctxh, *p_ctxl, *p_zh, *p_zl, *p_hh, *p_hl;
    uint16_t *p_rawh, *p_rawl, *p_qh, *p_ql, *p_cbh, *p_cbl;
    uint16_t *p_wrh, *p_wrl, *p_w1h, *p_w1l, *p_w2h, *p_w2l, *p_wsh, *p_wsl;
    float *p_scores, *p_cnorm;
    SA(p_tsh, g_ts_h);   SA(p_tsl, g_ts_l);
    SA(p_ctxh, g_ctx_h); SA(p_ctxl, g_ctx_l);
    SA(p_zh, g_z_h);     SA(p_zl, g_z_l);
    SA(p_hh, g_h_h);     SA(p_hl, g_h_l);
    SA(p_rawh, g_raw_h); SA(p_rawl, g_raw_l);
    SA(p_qh, g_q_h);     SA(p_ql, g_q_l);
    SA(p_cbh, g_cb_h);   SA(p_cbl, g_cb_l);
    SA(p_wrh, g_wr_h);   SA(p_wrl, g_wr_l);
    SA(p_w1h, g_w1_h);   SA(p_w1l, g_w1_l);
    SA(p_w2h, g_w2_h);   SA(p_w2l, g_w2_l);
    SA(p_wsh, g_ws_h);   SA(p_wsl, g_ws_l);
    SA(p_scores, g_scores);
    SA(p_cnorm, g_cnorm);

    cudaFuncSetAttribute(tgemm_mma<true, false, false>,
                         cudaFuncAttributeMaxDynamicSharedMemorySize, SMEM_BYTES);
    cudaFuncSetAttribute(tgemm_mma<false, false, false>,
                         cudaFuncAttributeMaxDynamicSharedMemorySize, SMEM_BYTES);
    cudaFuncSetAttribute(tgemm_mma<true, true, false>,
                         cudaFuncAttributeMaxDynamicSharedMemorySize, SMEM_BYTES);
    cudaFuncSetAttribute(tgemm_mma<false, false, true>,
                         cudaFuncAttributeMaxDynamicSharedMemorySize, SMEM_BYTES);

    dim3 tpb(32, 8);

    init_used_kernel<<<1, 32>>>();
    routing_kernel<<<N_TOK, 256>>>(bus_symbols, bus_outputs, Wq, bq);
    cnorm_kernel<<<NC / 8, 256>>>(codebook);
    split_bf16_kernel<<<(N_TOK * LAT / 4) / 256, 256>>>(token_state, p_tsh, p_tsl);
    split_bf16_kernel<<<(NC * SYM / 4) / 256, 256>>>(codebook, p_cbh, p_cbl);

    wprep_T<<<dim3(LAT / 32, 2 * LAT / 32), tpb>>>(Wread, 2 * LAT, LAT, p_wrh, p_wrl);
    wprep_T<<<dim3(SYM / 32, LAT / 32), tpb>>>(Wsym, LAT, SYM, p_wsh, p_wsl);
    wprep_T<<<dim3(LAT / 32, (LAT + SYM) / 32), tpb>>>(Wc1, LAT + SYM, LAT, p_w1h, p_w1l);
    wprep_T<<<dim3(LAT / 32, LAT / 32), tpb>>>(Wc2, LAT, LAT, p_w2h, p_w2l);

    // z = [ts | ctx] @ Wread + bread       -> bf16 pair
    tgemm_mma<true, false, false><<<dim3(LAT / 128, N_TOK / 128), 256, SMEM_BYTES>>>(
        p_tsh, p_tsl, p_ctxh, p_ctxl, LAT, 2 * LAT, p_wrh, p_wrl,
        bread, 1.0f, nullptr, nullptr, p_zh, p_zl, LAT);
    // raw = z @ Wsym + bsym                -> bf16 pair
    tgemm_mma<true, false, false><<<dim3(SYM / 128, N_TOK / 128), 256, SMEM_BYTES>>>(
        p_zh, p_zl, p_zh, p_zl, LAT, LAT, p_wsh, p_wsl,
        bsym, 1.0f, nullptr, nullptr, p_rawh, p_rawl, SYM);
    // scores = -2 * raw @ cb^T + ||c||^2   -> fp32
    tgemm_mma<false, false, false><<<dim3(NC / 128, N_TOK / 128), 256, SMEM_BYTES>>>(
        p_rawh, p_rawl, p_rawh, p_rawl, SYM, SYM, p_cbh, p_cbl,
        p_cnorm, -2.0f, nullptr, p_scores, nullptr, nullptr, NC);
    // argmin + quantized + indices
    argmin_gather_kernel<<<N_TOK / 8, 256>>>(codebook, out_quant, out_idx);
    // h = relu([z | quant] @ Wc1 + bc1)    -> bf16 pair
    tgemm_mma<true, true, false><<<dim3(LAT / 128, N_TOK / 128), 256, SMEM_BYTES>>>(
        p_zh, p_zl, p_qh, p_ql, LAT, LAT + SYM, p_w1h, p_w1l,
        bc1, 1.0f, nullptr, nullptr, p_hh, p_hl, LAT);
    // node = h @ Wc2 + bc2 + token_state   -> fp32
    tgemm_mma<false, false, true><<<dim3(LAT / 128, N_TOK / 128), 256, SMEM_BYTES>>>(
        p_hh, p_hl, p_hh, p_hl, LAT, LAT, p_w2h, p_w2l,
        bc2, 1.0f, token_state, out_node, nullptr, nullptr, LAT);

    keep_kernel<<<1, 32>>>(out_keep);
}

// round 15
// speedup vs baseline: 1.7497x; 1.0937x over previous
#include <cuda_runtime.h>
#include <cuda_bf16.h>
#include <cstdint>

// ---------------------------------------------------------------------------
// Problem constants
// ---------------------------------------------------------------------------
#define T_MSG 8
#define N_TOK 8192
#define LAT 1024
#define SYM 256
#define NC 512

#define OUT_QUANT_OFF ((size_t)N_TOK * LAT)
#define OUT_IDX_OFF   (OUT_QUANT_OFF + (size_t)N_TOK * SYM)
#define OUT_KEEP_OFF  (OUT_IDX_OFF + (size_t)N_TOK)

// ---------------------------------------------------------------------------
// Device scratch — all GEMM operands pre-split to bf16 hi/lo pairs
// ---------------------------------------------------------------------------
__device__ uint16_t g_ts_h[(size_t)N_TOK * LAT];
__device__ uint16_t g_ts_l[(size_t)N_TOK * LAT];
__device__ uint16_t g_ctx_h[(size_t)N_TOK * LAT];
__device__ uint16_t g_ctx_l[(size_t)N_TOK * LAT];
__device__ uint16_t g_z_h[(size_t)N_TOK * LAT];
__device__ uint16_t g_z_l[(size_t)N_TOK * LAT];
__device__ uint16_t g_h_h[(size_t)N_TOK * LAT];
__device__ uint16_t g_h_l[(size_t)N_TOK * LAT];
__device__ uint16_t g_raw_h[(size_t)N_TOK * SYM];
__device__ uint16_t g_raw_l[(size_t)N_TOK * SYM];
__device__ uint16_t g_q_h[(size_t)N_TOK * SYM];
__device__ uint16_t g_q_l[(size_t)N_TOK * SYM];
__device__ uint16_t g_cb_h[(size_t)NC * SYM];
__device__ uint16_t g_cb_l[(size_t)NC * SYM];

__device__ uint16_t g_wr_h[(size_t)LAT * 2 * LAT];
__device__ uint16_t g_wr_l[(size_t)LAT * 2 * LAT];
__device__ uint16_t g_w1_h[(size_t)LAT * (LAT + SYM)];
__device__ uint16_t g_w1_l[(size_t)LAT * (LAT + SYM)];
__device__ uint16_t g_w2_h[(size_t)LAT * LAT];
__device__ uint16_t g_w2_l[(size_t)LAT * LAT];
__device__ uint16_t g_ws_h[(size_t)SYM * LAT];
__device__ uint16_t g_ws_l[(size_t)SYM * LAT];

__device__ float g_scores[(size_t)N_TOK * NC];
__device__ float g_cnorm[NC];
__device__ int   g_used[T_MSG];

// ---------------------------------------------------------------------------
// Helpers
// ---------------------------------------------------------------------------
__device__ __forceinline__ uint32_t smem_u32(const void* p) {
    uint32_t a;
    asm("{ .reg .u64 t; cvta.to.shared.u64 t, %1; cvt.u32.u64 %0, t; }"
        : "=r"(a) : "l"(p));
    return a;
}
__device__ __forceinline__ void cp16(uint32_t dst, const void* src) {
    asm volatile("cp.async.cg.shared.global [%0], [%1], 16;"
                 :: "r"(dst), "l"(src));
}
#define CP_COMMIT() asm volatile("cp.async.commit_group;" ::: "memory")
#define CP_WAIT1()  asm volatile("cp.async.wait_group 1;" ::: "memory")

// bf16 split of a float2: hi = bf16x2(v), lo = bf16x2(v - float(hi))
__device__ __forceinline__ void bf16_split2(float2 v, uint32_t& hi, uint32_t& lo) {
    __nv_bfloat162 h = __float22bfloat162_rn(v);
    hi = *reinterpret_cast<uint32_t*>(&h);
    float hx = __uint_as_float(hi << 16);
    float hy = __uint_as_float(hi & 0xffff0000u);
    __nv_bfloat162 m = __float22bfloat162_rn(make_float2(v.x - hx, v.y - hy));
    lo = *reinterpret_cast<uint32_t*>(&m);
}
__device__ __forceinline__ void bf16_split1(float v, uint16_t& hi, uint16_t& lo) {
    __nv_bfloat16 h = __float2bfloat16_rn(v);
    hi = *reinterpret_cast<uint16_t*>(&h);
    float hf = __uint_as_float(((uint32_t)hi) << 16);
    __nv_bfloat16 m = __float2bfloat16_rn(v - hf);
    lo = *reinterpret_cast<uint16_t*>(&m);
}

#define MMA16(d, a, b) \
    asm volatile( \
        "mma.sync.aligned.m16n8k16.row.col.f32.bf16.bf16.f32 " \
        "{%0,%1,%2,%3}, {%4,%5,%6,%7}, {%8,%9}, {%0,%1,%2,%3};" \
        : "+f"((d)[0]), "+f"((d)[1]), "+f"((d)[2]), "+f"((d)[3]) \
        : "r"((a)[0]), "r"((a)[1]), "r"((a)[2]), "r"((a)[3]), \
          "r"((b)[0]), "r"((b)[1]))

// ---------------------------------------------------------------------------
// bf16x3 mma.sync GEMM on pre-split operands:
//   Out = alpha*(A @ B^T) + bias (+res)(relu)
// A = [A1|A2] along K (bf16 hi/lo [M,K]); B bf16 hi/lo [N,K].
// CTA tile 64x128, BK=32, 8 warps (2x4), warp tile 32x32, 2 CTAs/SM.
// SMEM rows 80B (32 bf16 + pad) - conflict-free. Pure LDS.32 + MMA mainloop.
// ---------------------------------------------------------------------------
#define STG_B 30720                  // bytes/stage: A hi/lo 2*5120 + B hi/lo 2*10240
#define SMEM_BYTES (2 * STG_B)       // 61440 -> 2 CTAs/SM

template <bool SPLIT, bool RELU, bool HAS_RES>
__global__ __launch_bounds__(256, 2)
void tgemm_mma(const uint16_t* __restrict__ A1h, const uint16_t* __restrict__ A1l,
               const uint16_t* __restrict__ A2h, const uint16_t* __restrict__ A2l,
               int K1, int K,
               const uint16_t* __restrict__ Bh, const uint16_t* __restrict__ Bl,
               const float* __restrict__ bias, float alpha,
               const float* __restrict__ residual,
               float* __restrict__ Ofp,
               uint16_t* __restrict__ Oh, uint16_t* __restrict__ Ol,
               int Ntot) {
    extern __shared__ __align__(16) char smc[];
    const int tid = threadIdx.x;
    const int lane = tid & 31, wid = tid >> 5;
    const int wm = wid >> 2, wn = wid & 3;        // 2 x 4 warp grid
    const int m0 = blockIdx.y << 6, n0 = blockIdx.x << 7;
    const uint32_t sbase = smem_u32(smc);

    float acc[2][4][4];
    #pragma unroll
    for (int mi = 0; mi < 2; mi++)
        #pragma unroll
        for (int ni = 0; ni < 4; ni++)
            #pragma unroll
            for (int r = 0; r < 4; r++) acc[mi][ni][r] = 0.f;

    const int nc = K >> 5;

    auto stage = [&](int s, int c) {
        const int k0 = c << 5;
        const uint32_t sb = sbase + (uint32_t)s * STG_B;
        // A: 64 rows x 4 x 16B segs = 256 ops (1 per thread) for hi, lo paired
        {
            int row = tid >> 2, seg = tid & 3;
            int kk = k0 + (seg << 3);
            const uint16_t *ph, *pl;
            if (kk < K1) {
                size_t o = (size_t)(m0 + row) * K1 + kk;
                ph = A1h + o; pl = A1l + o;
            } else {
                size_t o = (size_t)(m0 + row) * (K - K1) + (kk - K1);
                ph = A2h + o; pl = A2l + o;
            }
            uint32_t d = sb + (uint32_t)(row * 80 + (seg << 4));
            cp16(d, ph);
            cp16(d + 5120, pl);
        }
        // B: 128 rows x 4 segs = 512 ops (2 per thread)
        #pragma unroll
        for (int it = 0; it < 2; ++it) {
            int idx = tid + (it << 8);
            int row = idx >> 2, seg = idx & 3;
            size_t o = (size_t)(n0 + row) * K + k0 + (seg << 3);
            uint32_t d = sb + 10240u + (uint32_t)(row * 80 + (seg << 4));
            cp16(d, Bh + o);
            cp16(d + 10240, Bl + o);
        }
    };

    stage(0, 0);
    CP_COMMIT();

    const int am = (wm << 5) + (lane >> 2);
    const int bn = (wn << 5) + (lane >> 2);

    for (int c = 0; c < nc; ++c) {
        if (c + 1 < nc) stage((c + 1) & 1, c + 1);
        CP_COMMIT();
        CP_WAIT1();
        __syncthreads();

        const char* base = smc + (c & 1) * STG_B;
        const char* sAh = base;
        const char* sAl = base + 5120;
        const char* sBh = base + 10240;
        const char* sBl = base + 20480;

        #pragma unroll
        for (int kk = 0; kk < 2; ++kk) {       // two k16 blocks per BK=32
            const int kbyte = (kk << 5) + ((lane & 3) << 2);
            uint32_t ah[2][4], al[2][4], bh[4][2], bl[4][2];
            #pragma unroll
            for (int mi = 0; mi < 2; mi++) {
                int ro = (am + (mi << 4)) * 80 + kbyte;
                ah[mi][0] = *reinterpret_cast<const uint32_t*>(sAh + ro);
                ah[mi][1] = *reinterpret_cast<const uint32_t*>(sAh + ro + 640);
                ah[mi][2] = *reinterpret_cast<const uint32_t*>(sAh + ro + 16);
                ah[mi][3] = *reinterpret_cast<const uint32_t*>(sAh + ro + 656);
                al[mi][0] = *reinterpret_cast<const uint32_t*>(sAl + ro);
                al[mi][1] = *reinterpret_cast<const uint32_t*>(sAl + ro + 640);
                al[mi][2] = *reinterpret_cast<const uint32_t*>(sAl + ro + 16);
                al[mi][3] = *reinterpret_cast<const uint32_t*>(sAl + ro + 656);
            }
            #pragma unroll
            for (int ni = 0; ni < 4; ni++) {
                int ro = (bn + (ni << 3)) * 80 + kbyte;
                bh[ni][0] = *reinterpret_cast<const uint32_t*>(sBh + ro);
                bh[ni][1] = *reinterpret_cast<const uint32_t*>(sBh + ro + 16);
                bl[ni][0] = *reinterpret_cast<const uint32_t*>(sBl + ro);
                bl[ni][1] = *reinterpret_cast<const uint32_t*>(sBl + ro + 16);
            }
            // pass 1: hi * hi
            #pragma unroll
            for (int mi = 0; mi < 2; mi++)
                #pragma unroll
                for (int ni = 0; ni < 4; ni++) MMA16(acc[mi][ni], ah[mi], bh[ni]);
            // pass 2: hi * lo
            #pragma unroll
            for (int mi = 0; mi < 2; mi++)
                #pragma unroll
                for (int ni = 0; ni < 4; ni++) MMA16(acc[mi][ni], ah[mi], bl[ni]);
            // pass 3: lo * hi
            #pragma unroll
            for (int mi = 0; mi < 2; mi++)
                #pragma unroll
                for (int ni = 0; ni < 4; ni++) MMA16(acc[mi][ni], al[mi], bh[ni]);
        }
        __syncthreads();
    }

    // ---- epilogue ----
    #pragma unroll
    for (int mi = 0; mi < 2; mi++) {
        #pragma unroll
        for (int ni = 0; ni < 4; ni++) {
            int r = m0 + (wm << 5) + (mi << 4) + (lane >> 2);
            int nn = n0 + (wn << 5) + (ni << 3) + ((lane & 3) << 1);
            float b0 = bias[nn], b1 = bias[nn + 1];
            #pragma unroll
            for (int half = 0; half < 2; half++) {
                int rr = r + half * 8;
                float v0 = alpha * acc[mi][ni][half * 2 + 0] + b0;
                float v1 = alpha * acc[mi][ni][half * 2 + 1] + b1;
                if (HAS_RES) {
                    const float2 rv = *reinterpret_cast<const float2*>(
                        residual + (size_t)rr * Ntot + nn);
                    v0 += rv.x; v1 += rv.y;
                }
                if (RELU) { v0 = fmaxf(v0, 0.f); v1 = fmaxf(v1, 0.f); }
                if (SPLIT) {
                    uint32_t h, l;
                    bf16_split2(make_float2(v0, v1), h, l);
                    *reinterpret_cast<uint32_t*>(Oh + (size_t)rr * Ntot + nn) = h;
                    *reinterpret_cast<uint32_t*>(Ol + (size_t)rr * Ntot + nn) = l;
                } else {
                    *reinterpret_cast<float2*>(Ofp + (size_t)rr * Ntot + nn) =
                        make_float2(v0, v1);
                }
            }
        }
    }
}

// ---------------------------------------------------------------------------
// Prep / small kernels
// ---------------------------------------------------------------------------
__global__ void init_used_kernel() {
    if (threadIdx.x < T_MSG) g_used[threadIdx.x] = 0;
}

// elementwise fp32 -> bf16 hi/lo (float4 per thread)
__global__ void split_bf16_kernel(const float* __restrict__ in,
                                  uint16_t* __restrict__ hi,
                                  uint16_t* __restrict__ lo) {
    int i = blockIdx.x * 256 + threadIdx.x;
    float4 v = reinterpret_cast<const float4*>(in)[i];
    uint32_t h0, l0, h1, l1;
    bf16_split2(make_float2(v.x, v.y), h0, l0);
    bf16_split2(make_float2(v.z, v.w), h1, l1);
    reinterpret_cast<uint2*>(hi)[i] = make_uint2(h0, h1);
    reinterpret_cast<uint2*>(lo)[i] = make_uint2(l0, l1);
}

// routing + ctx gather/split + token_state split (fused; one block per token)
__global__ void routing_kernel(const float* __restrict__ bus_symbols,
                               const float* __restrict__ bus_outputs,
                               const float* __restrict__ token_state,
                               const float* __restrict__ Wq,
                               const float* __restrict__ bq) {
    int n = blockIdx.x;
    int tid = threadIdx.x;
    int lane = tid & 31, warp = tid >> 5;
    __shared__ float sWq[SYM];
    __shared__ float sRed[8];
    __shared__ int sTop;
    sWq[tid] = Wq[tid];
    __syncthreads();

    // token_state split (independent of routing result)
    {
        float4 v = reinterpret_cast<const float4*>(
            token_state + (size_t)n * LAT)[tid];
        uint32_t h0, l0, h1, l1;
        bf16_split2(make_float2(v.x, v.y), h0, l0);
        bf16_split2(make_float2(v.z, v.w), h1, l1);
        size_t off = (size_t)n * LAT;
        reinterpret_cast<uint2*>(g_ts_h + off)[tid] = make_uint2(h0, h1);
        reinterpret_cast<uint2*>(g_ts_l + off)[tid] = make_uint2(l0, l1);
    }

    float best = -3.4e38f;
    int bt = 0;
    for (int t = 0; t < T_MSG; t++) {
        float v = bus_symbols[((size_t)t * N_TOK + n) * SYM + tid] * sWq[tid];
        #pragma unroll
        for (int off = 16; off > 0; off >>= 1)
            v += __shfl_down_sync(0xffffffffu, v, off);
        if (lane == 0) sRed[warp] = v;
        __syncthreads();
        if (tid == 0) {
            float r = sRed[0] + sRed[1] + sRed[2] + sRed[3]
                    + sRed[4] + sRed[5] + sRed[6] + sRed[7] + bq[0];
            if (r > best) { best = r; bt = t; }
        }
        __syncthreads();
    }
    if (tid == 0) { sTop = bt; atomicExch(&g_used[bt], 1); }
    __syncthreads();
    int top = sTop;
    float4 v = reinterpret_cast<const float4*>(
        bus_outputs + ((size_t)top * N_TOK + n) * LAT)[tid];
    uint32_t h0, l0, h1, l1;
    bf16_split2(make_float2(v.x, v.y), h0, l0);
    bf16_split2(make_float2(v.z, v.w), h1, l1);
    size_t off = (size_t)n * LAT;
    reinterpret_cast<uint2*>(g_ctx_h + off)[tid] = make_uint2(h0, h1);
    reinterpret_cast<uint2*>(g_ctx_l + off)[tid] = make_uint2(l0, l1);
}

__global__ void keep_kernel(float* __restrict__ out_keep) {
    if (threadIdx.x < T_MSG)
        out_keep[threadIdx.x] = (g_used[threadIdx.x] == 0) ? 1.0f : 0.0f;
}

__global__ void cnorm_kernel(const float* __restrict__ codebook) {
    int c = blockIdx.x * (blockDim.x >> 5) + (threadIdx.x >> 5);
    int lane = threadIdx.x & 31;
    if (c >= NC) return;
    float s = 0.f;
    const float* row = codebook + (size_t)c * SYM;
    #pragma unroll
    for (int i = 0; i < SYM / 32; i++) {
        float v = row[lane + i * 32];
        s += v * v;
    }
    #pragma unroll
    for (int off = 16; off > 0; off >>= 1)
        s += __shfl_down_sync(0xffffffffu, s, off);
    if (lane == 0) g_cnorm[c] = s;
}

// transpose + bf16 split: W [K,N] fp32 -> hi/lo [N,K] bf16
__global__ void wprep_T(const float* __restrict__ W, int K, int N,
                        uint16_t* __restrict__ Wh, uint16_t* __restrict__ Wl) {
    __shared__ float t[32][33];
    int k0 = blockIdx.y << 5, n0 = blockIdx.x << 5;
    int tx = threadIdx.x, ty = threadIdx.y;
    #pragma unroll
    for (int i = 0; i < 32; i += 8)
        t[ty + i][tx] = W[(size_t)(k0 + ty + i) * N + n0 + tx];
    __syncthreads();
    #pragma unroll
    for (int i = 0; i < 32; i += 8) {
        float v = t[tx][ty + i];
        uint16_t h, l;
        bf16_split1(v, h, l);
        size_t o = (size_t)(n0 + ty + i) * K + k0 + tx;
        Wh[o] = h;
        Wl[o] = l;
    }
}

__global__ void argmin_gather_kernel(const float* __restrict__ codebook,
                                     float* __restrict__ out_quant,
                                     float* __restrict__ out_idx) {
    int warp = threadIdx.x >> 5, lane = threadIdx.x & 31;
    int n = blockIdx.x * 8 + warp;
    const float* sc = g_scores + (size_t)n * NC;
    float best = 3.4e38f;
    int bi = 0;
    #pragma unroll
    for (int w = 0; w < NC / 32; w++) {
        int c = lane + w * 32;
        float v = sc[c];
        if (v < best) { best = v; bi = c; }
    }
    #pragma unroll
    for (int off = 16; off > 0; off >>= 1) {
        float ov = __shfl_xor_sync(0xffffffffu, best, off);
        int   oi = __shfl_xor_sync(0xffffffffu, bi, off);
        if (ov < best || (ov == best && oi < bi)) { best = ov; bi = oi; }
    }
    bi = __shfl_sync(0xffffffffu, bi, 0);
    if (lane == 0) out_idx[n] = (float)bi;
    const float* crow = codebook + (size_t)bi * SYM;
    const uint16_t* ch = g_cb_h + (size_t)bi * SYM;
    const uint16_t* cl = g_cb_l + (size_t)bi * SYM;
    float* qrow = out_quant + (size_t)n * SYM;
    uint16_t* qh = g_q_h + (size_t)n * SYM;
    uint16_t* ql = g_q_l + (size_t)n * SYM;
    #pragma unroll
    for (int j = 0; j < SYM / 32; j++) {
        int c = lane + j * 32;
        qrow[c] = crow[c];
        qh[c] = ch[c];
        ql[c] = cl[c];
    }
}

// ---------------------------------------------------------------------------
// Launch
// ---------------------------------------------------------------------------
extern "C" void kernel_launch(void* const* d_in, const int* in_sizes, int n_in,
                              void* d_out, int out_size) {
    const float* token_state = (const float*)d_in[0];
    const float* bus_symbols = (const float*)d_in[1];
    const float* bus_outputs = (const float*)d_in[3];
    const float* Wq    = (const float*)d_in[5];
    const float* bq    = (const float*)d_in[6];
    const float* Wread = (const float*)d_in[7];
    const float* bread = (const float*)d_in[8];
    const float* Wsym  = (const float*)d_in[9];
    const float* bsym  = (const float*)d_in[10];
    const float* Wc1   = (const float*)d_in[11];
    const float* bc1   = (const float*)d_in[12];
    const float* Wc2   = (const float*)d_in[13];
    const float* bc2   = (const float*)d_in[14];
    const float* codebook = (const float*)d_in[15];

    float* out = (float*)d_out;
    float* out_node  = out;
    float* out_quant = out + OUT_QUANT_OFF;
    float* out_idx   = out + OUT_IDX_OFF;
    float* out_keep  = out + OUT_KEEP_OFF;

    #define SA(p, s) cudaGetSymbolAddress((void**)&p, s)
    uint16_t *p_tsh, *p_tsl, *p_ctxh, *p_ctxl, *p_zh, *p_zl, *p_hh, *p_hl;
    uint16_t *p_rawh, *p_rawl, *p_qh, *p_ql, *p_cbh, *p_cbl;
    uint16_t *p_wrh, *p_wrl, *p_w1h, *p_w1l, *p_w2h, *p_w2l, *p_wsh, *p_wsl;
    float *p_scores, *p_cnorm;
    SA(p_tsh, g_ts_h);   SA(p_tsl, g_ts_l);
    SA(p_ctxh, g_ctx_h); SA(p_ctxl, g_ctx_l);
    SA(p_zh, g_z_h);     SA(p_zl, g_z_l);
    SA(p_hh, g_h_h);     SA(p_hl, g_h_l);
    SA(p_rawh, g_raw_h); SA(p_rawl, g_raw_l);
    SA(p_qh, g_q_h);     SA(p_ql, g_q_l);
    SA(p_cbh, g_cb_h);   SA(p_cbl, g_cb_l);
    SA(p_wrh, g_wr_h);   SA(p_wrl, g_wr_l);
    SA(p_w1h, g_w1_h);   SA(p_w1l, g_w1_l);
    SA(p_w2h, g_w2_h);   SA(p_w2l, g_w2_l);
    SA(p_wsh, g_ws_h);   SA(p_wsl, g_ws_l);
    SA(p_scores, g_scores);
    SA(p_cnorm, g_cnorm);

    cudaFuncSetAttribute(tgemm_mma<true, false, false>,
                         cudaFuncAttributeMaxDynamicSharedMemorySize, SMEM_BYTES);
    cudaFuncSetAttribute(tgemm_mma<false, false, false>,
                         cudaFuncAttributeMaxDynamicSharedMemorySize, SMEM_BYTES);
    cudaFuncSetAttribute(tgemm_mma<true, true, false>,
                         cudaFuncAttributeMaxDynamicSharedMemorySize, SMEM_BYTES);
    cudaFuncSetAttribute(tgemm_mma<false, false, true>,
                         cudaFuncAttributeMaxDynamicSharedMemorySize, SMEM_BYTES);

    dim3 tpb(32, 8);

    init_used_kernel<<<1, 32>>>();
    routing_kernel<<<N_TOK, 256>>>(bus_symbols, bus_outputs, token_state, Wq, bq);
    cnorm_kernel<<<NC / 8, 256>>>(codebook);
    split_bf16_kernel<<<(NC * SYM / 4) / 256, 256>>>(codebook, p_cbh, p_cbl);

    wprep_T<<<dim3(LAT / 32, 2 * LAT / 32), tpb>>>(Wread, 2 * LAT, LAT, p_wrh, p_wrl);
    wprep_T<<<dim3(SYM / 32, LAT / 32), tpb>>>(Wsym, LAT, SYM, p_wsh, p_wsl);
    wprep_T<<<dim3(LAT / 32, (LAT + SYM) / 32), tpb>>>(Wc1, LAT + SYM, LAT, p_w1h, p_w1l);
    wprep_T<<<dim3(LAT / 32, LAT / 32), tpb>>>(Wc2, LAT, LAT, p_w2h, p_w2l);

    // z = [ts | ctx] @ Wread + bread       -> bf16 pair
    tgemm_mma<true, false, false><<<dim3(LAT / 128, N_TOK / 64), 256, SMEM_BYTES>>>(
        p_tsh, p_tsl, p_ctxh, p_ctxl, LAT, 2 * LAT, p_wrh, p_wrl,
        bread, 1.0f, nullptr, nullptr, p_zh, p_zl, LAT);
    // raw = z @ Wsym + bsym                -> bf16 pair
    tgemm_mma<true, false, false><<<dim3(SYM / 128, N_TOK / 64), 256, SMEM_BYTES>>>(
        p_zh, p_zl, p_zh, p_zl, LAT, LAT, p_wsh, p_wsl,
        bsym, 1.0f, nullptr, nullptr, p_rawh, p_rawl, SYM);
    // scores = -2 * raw @ cb^T + ||c||^2   -> fp32
    tgemm_mma<false, false, false><<<dim3(NC / 128, N_TOK / 64), 256, SMEM_BYTES>>>(
        p_rawh, p_rawl, p_rawh, p_rawl, SYM, SYM, p_cbh, p_cbl,
        p_cnorm, -2.0f, nullptr, p_scores, nullptr, nullptr, NC);
    // argmin + quantized + indices
    argmin_gather_kernel<<<N_TOK / 8, 256>>>(codebook, out_quant, out_idx);
    // h = relu([z | quant] @ Wc1 + bc1)    -> bf16 pair
    tgemm_mma<true, true, false><<<dim3(LAT / 128, N_TOK / 64), 256, SMEM_BYTES>>>(
        p_zh, p_zl, p_qh, p_ql, LAT, LAT + SYM, p_w1h, p_w1l,
        bc1, 1.0f, nullptr, nullptr, p_hh, p_hl, LAT);
    // node = h @ Wc2 + bc2 + token_state   -> fp32
    tgemm_mma<false, false, true><<<dim3(LAT / 128, N_TOK / 64), 256, SMEM_BYTES>>>(
        p_hh, p_hl, p_hh, p_hl, LAT, LAT, p_w2h, p_w2l,
        bc2, 1.0f, token_state, out_node, nullptr, nullptr, LAT);

    keep_kernel<<<1, 32>>>(out_keep);
}